// round 10
// baseline (speedup 1.0000x reference)
#include <cuda_runtime.h>
#include <cuda_bf16.h>

#define NT 2000
#define NS 512
#define NH 64

// Output packing (concatenated flattened tuple, float32):
//   Q  : [NT, NS]        at 0
//   C  : [NT, NS]        at 1,024,000
//   S  : [NT, NS, NH]    at 2,048,000
//   H1 : [NT, NS, NH]    at 67,584,000
//   H2 : [NT, NS, NH]    at 133,120,000
//   Qs : [NT, NS, 3]     at 198,656,000
#define OFF_C   1024000
#define OFF_S   2048000
#define OFF_H1  67584000
#define OFF_H2  133120000
#define OFF_QS  198656000

__device__ __forceinline__ float sigmoidf(float x) {
    return 1.0f / (1.0f + expf(-x));
}

// pbuf row layout: 66 float4 slots per step. Warp w's lane l writes slot
// w*33 + l (gap at slot 32) so phase-2's half-row reads land on disjoint
// bank groups (conflict-free 4-phase LDS.128).
#define PROW 66

__global__ void __launch_bounds__(64, 8)
soil_cq_kernel(const float* __restrict__ P, const float* __restrict__ T,
               const float* __restrict__ E,
               const float* __restrict__ w,  const float* __restrict__ wk1,
               const float* __restrict__ wk2, const float* __restrict__ we1,
               const float* __restrict__ we2, const float* __restrict__ wl,
               const float* __restrict__ wo,  const float* __restrict__ wc,
               float* __restrict__ out)
{
    const int tid  = threadIdx.x;      // 0..63
    const int lane = tid & 31;
    const int wrp  = tid >> 5;         // 0..1
    const int site = blockIdx.x;       // 0..511
    const int j    = tid;              // hidden unit, 1 per thread

    __shared__ float4 pbuf[32][PROW];  // per-step per-unit partials (q1a,q2a,qc,_)
    __shared__ float4 fbuf[2][32];     // double-buffered forcing chunks (p,t,e,_)
    __shared__ float  smred[2];

    float* fb = (float*)fbuf;

    // ---- per-unit parameter precompute ----
    const float ew   = expf(w[j]) + 1.0f;
    const float sk1  = sigmoidf(wk1[j]);
    const float sk2  = sigmoidf(wk2[j]);
    const float se1  = sigmoidf(we1[j]);
    const float se2  = sigmoidf(we2[j]);
    const float L    = expf(wl[j]);
    const float csk1 = 1.0f - sk1;          // h1a - q1 = h1a*csk1
    const float csk2 = 1.0f - 2.0f * sk2;   // h2a - 2*q2 = h2a*csk2

    // softmax(wo) over 64 units: warp butterfly + cross-warp smem combine
    const float ex = expf(wo[j]);
    float esum = ex;
    #pragma unroll
    for (int o = 16; o; o >>= 1) esum += __shfl_xor_sync(0xffffffffu, esum, o);
    if (lane == 0) smred[wrp] = esum;

    // stage chunk-0 forcings while the softmax barrier is pending
    if (tid < 32) {
        fb[tid * 4 + 0] = P[tid * NS + site];
        fb[tid * 4 + 1] = T[tid * NS + site];
    } else {
        fb[(tid - 32) * 4 + 2] = E[(tid - 32) * NS + site];
    }
    __syncthreads();

    esum = smred[0] + smred[1];
    const float a  = ex / esum;
    const float ar = a / (sk2 * (1.0f + expf(wc[j])));

    // ---- state in registers ----
    float s = 0.f, h1 = 0.f, h2 = 0.f;

    // ---- coalesced state pointers: each warp stores 128B/array/step ----
    float* Sp  = out + OFF_S  + (size_t)site * NH + j;
    float* H1p = out + OFF_H1 + (size_t)site * NH + j;
    float* H2p = out + OFF_H2 + (size_t)site * NH + j;

    const int pslot = wrp * 33 + lane;     // padded partial slot for this unit

    for (int t0 = 0; t0 < NT; t0 += 32) {
        const int buf = (t0 >> 5) & 1;
        const int rem = (NT - t0 < 32) ? (NT - t0) : 32;

        // prefetch next chunk's forcings into registers
        float f0 = 0.f, f1 = 0.f;
        if (tid < 32) {
            const int tn = t0 + 32 + tid;
            if (tn < NT) { f0 = P[tn * NS + site]; f1 = T[tn * NS + site]; }
        } else {
            const int tn = t0 + tid;       // t0 + 32 + (tid-32)
            if (tn < NT) f0 = E[tn * NS + site];
        }

        __syncthreads();   // prev phase-2 done with pbuf; fbuf[buf] staged

        // ================= phase 1: recurrence, no shuffles =================
        #pragma unroll 8
        for (int i = 0; i < rem; ++i) {
            const float4 f = fbuf[buf][i];
            const float p = f.x, t = f.y, e = f.z;

            const float trel = fmaxf(t, 0.0f);
            const float ppos = (t > 0.0f) ? p : 0.0f;
            const float pneg = (t < 0.0f) ? p : 0.0f;

            const float m   = fminf(trel * ew, s);
            s = s - m + pneg;
            const float x   = ppos + m;
            const float h2x = h2 + x;
            const float h1a = fmaxf(h1 + h2x - L, 0.0f);
            const float h2a = fminf(h1a + h2x, L);
            const float q1  = h1a * sk1;
            const float q2  = h2a * sk2;
            h1 = fmaxf(fmaf(h1a, csk1, -e * se1), 0.0f);
            h2 = fmaxf(fmaf(h2a, csk2, -e * se2), 0.0f);

            *Sp  = s;
            *H1p = h1;
            *H2p = h2;
            Sp  += NS * NH;
            H1p += NS * NH;
            H2p += NS * NH;

            pbuf[i][pslot] = make_float4(q1 * a, q2 * a, q2 * ar, 0.f);
        }

        // stage next chunk's forcings
        if (tid < 32) {
            fb[((buf ^ 1) * 32 + tid) * 4 + 0] = f0;
            fb[((buf ^ 1) * 32 + tid) * 4 + 1] = f1;
        } else {
            fb[((buf ^ 1) * 32 + (tid - 32)) * 4 + 2] = f0;
        }

        __syncthreads();   // pbuf complete; fbuf[buf^1] staged

        // ====== phase 2: 2 lanes per step, each sums one warp's 32 partials ======
        const int step = wrp * 16 + (lane >> 1);
        const int half = lane & 1;
        const float4* row = &pbuf[step][half * 33];

        float x0 = 0.f, x1 = 0.f, x2 = 0.f, x3 = 0.f;
        float y0 = 0.f, y1 = 0.f, y2 = 0.f, y3 = 0.f;
        float z0 = 0.f, z1 = 0.f, z2 = 0.f, z3 = 0.f;
        #pragma unroll
        for (int k = 0; k < 32; k += 4) {
            const float4 v0 = row[k],     v1 = row[k + 1];
            const float4 v2 = row[k + 2], v3 = row[k + 3];
            x0 += v0.x; x1 += v1.x; x2 += v2.x; x3 += v3.x;
            y0 += v0.y; y1 += v1.y; y2 += v2.y; y3 += v3.y;
            z0 += v0.z; z1 += v1.z; z2 += v2.z; z3 += v3.z;
        }
        float Qs1 = (x0 + x1) + (x2 + x3);
        float Qs2 = (y0 + y1) + (y2 + y3);
        float qcS = (z0 + z1) + (z2 + z3);
        // combine the two halves (pairwise butterfly; all lanes participate)
        Qs1 += __shfl_xor_sync(0xffffffffu, Qs1, 1);
        Qs2 += __shfl_xor_sync(0xffffffffu, Qs2, 1);
        qcS += __shfl_xor_sync(0xffffffffu, qcS, 1);

        if (step < rem) {
            const int t = t0 + step;
            const float Qk = Qs1 + Qs2;
            if (half == 0) {
                out[t * NS + site] = Qk;
                float* qs = out + OFF_QS + ((size_t)t * NS + site) * 3;
                qs[0] = Qs1;
                qs[1] = Qs2;
                qs[2] = 0.0f;
            } else {
                out[OFF_C + t * NS + site] =
                    __fdividef(qcS * (1.0f / 64.0f) + 1e-5f, Qk + 1e-5f);
            }
        }
    }
}

extern "C" void kernel_launch(void* const* d_in, const int* in_sizes, int n_in,
                              void* d_out, int out_size)
{
    (void)in_sizes; (void)n_in; (void)out_size;
    soil_cq_kernel<<<NS, 64>>>(
        (const float*)d_in[0], (const float*)d_in[1], (const float*)d_in[2],
        (const float*)d_in[3], (const float*)d_in[4], (const float*)d_in[5],
        (const float*)d_in[6], (const float*)d_in[7], (const float*)d_in[8],
        (const float*)d_in[9], (const float*)d_in[10],
        (float*)d_out);
}

// round 11
// speedup vs baseline: 1.3079x; 1.3079x over previous
#include <cuda_runtime.h>
#include <cuda_bf16.h>

#define NT 2000
#define NS 512
#define NH 64

// Output packing (concatenated flattened tuple, float32):
//   Q  : [NT, NS]        at 0
//   C  : [NT, NS]        at 1,024,000
//   S  : [NT, NS, NH]    at 2,048,000
//   H1 : [NT, NS, NH]    at 67,584,000
//   H2 : [NT, NS, NH]    at 133,120,000
//   Qs : [NT, NS, 3]     at 198,656,000
#define OFF_C   1024000
#define OFF_S   2048000
#define OFF_H1  67584000
#define OFF_H2  133120000
#define OFF_QS  198656000

// per-half partial sums: [half][t*NS + site] -> (Qs1_h, Qs2_h, qc_h, 0)
__device__ float4 g_scratch[2 * NT * NS];

__device__ __forceinline__ float sigmoidf(float x) {
    return 1.0f / (1.0f + expf(-x));
}

__global__ void __launch_bounds__(32, 16)
soil_cq_kernel(const float* __restrict__ P, const float* __restrict__ T,
               const float* __restrict__ E,
               const float* __restrict__ w,  const float* __restrict__ wk1,
               const float* __restrict__ wk2, const float* __restrict__ we1,
               const float* __restrict__ we2, const float* __restrict__ wl,
               const float* __restrict__ wo,  const float* __restrict__ wc,
               float* __restrict__ out)
{
    const int lane = threadIdx.x;            // 0..31
    const int site = blockIdx.x >> 1;        // 0..511
    const int half = blockIdx.x & 1;         // which 32-unit half
    const int j    = half * 32 + lane;       // hidden unit (1 per lane)

    // [step][lane] partials, float4-packed, padded to 33 for conflict-free
    // transposed LDS.128 in phase 2
    __shared__ float4 pbuf[32][33];
    __shared__ float4 fbuf[2][32];            // forcing chunks (p,t,e,_)

    // ---- per-unit parameter precompute ----
    const float ew   = expf(w[j]) + 1.0f;
    const float sk1  = sigmoidf(wk1[j]);
    const float sk2  = sigmoidf(wk2[j]);
    const float se1  = sigmoidf(we1[j]);
    const float se2  = sigmoidf(we2[j]);
    const float L    = expf(wl[j]);
    const float csk1 = 1.0f - sk1;            // h1a - q1 = h1a*csk1
    const float csk2 = 1.0f - 2.0f * sk2;     // h2a - 2*q2 = h2a*csk2

    // softmax(wo) over ALL 64 units (each block loads both halves)
    const float e0 = expf(wo[lane]);
    const float e1 = expf(wo[lane + 32]);
    float esum = e0 + e1;
    #pragma unroll
    for (int o = 16; o; o >>= 1) esum += __shfl_xor_sync(0xffffffffu, esum, o);
    const float a  = (half ? e1 : e0) / esum;
    const float ar = a / (sk2 * (1.0f + expf(wc[j])));

    // ---- state in registers ----
    float s = 0.f, h1 = 0.f, h2 = 0.f;

    // ---- coalesced state pointers (128B per array per step per block) ----
    float* Sp  = out + OFF_S  + (size_t)site * NH + j;
    float* H1p = out + OFF_H1 + (size_t)site * NH + j;
    float* H2p = out + OFF_H2 + (size_t)site * NH + j;

    float4* scr = g_scratch + (size_t)half * (NT * NS) + site;

    // ---- stage chunk-0 forcings ----
    fbuf[0][lane] = make_float4(P[lane * NS + site],
                                T[lane * NS + site],
                                E[lane * NS + site], 0.f);

    for (int t0 = 0; t0 < NT; t0 += 32) {
        const int buf = (t0 >> 5) & 1;
        const int rem = (NT - t0 < 32) ? (NT - t0) : 32;

        // prefetch next chunk's forcings into registers (LDG hidden under phase 1)
        float pN = 0.f, tN = 0.f, eN = 0.f;
        {
            const int tn = t0 + 32 + lane;
            if (tn < NT) {
                pN = P[tn * NS + site];
                tN = T[tn * NS + site];
                eN = E[tn * NS + site];
            }
        }

        __syncwarp();   // fbuf[buf] staged; prev phase-2 done reading pbuf

        // ================= phase 1: recurrence, no shuffles =================
        #pragma unroll 8
        for (int i = 0; i < rem; ++i) {
            const float4 f = fbuf[buf][i];
            const float p = f.x, t = f.y, e = f.z;

            const float trel = fmaxf(t, 0.0f);
            const float ppos = (t > 0.0f) ? p : 0.0f;
            const float pneg = (t < 0.0f) ? p : 0.0f;

            const float m   = fminf(trel * ew, s);
            s = s - m + pneg;
            const float x   = ppos + m;
            const float h2x = h2 + x;
            const float h1a = fmaxf(h1 + h2x - L, 0.0f);
            const float h2a = fminf(h1a + h2x, L);
            const float q1  = h1a * sk1;
            const float q2  = h2a * sk2;
            h1 = fmaxf(fmaf(h1a, csk1, -e * se1), 0.0f);
            h2 = fmaxf(fmaf(h2a, csk2, -e * se2), 0.0f);

            *Sp  = s;
            *H1p = h1;
            *H2p = h2;
            Sp  += NS * NH;
            H1p += NS * NH;
            H2p += NS * NH;

            pbuf[i][lane] = make_float4(q1 * a, q2 * a, q2 * ar, 0.f);
        }

        // stage next chunk's forcings
        fbuf[buf ^ 1][lane] = make_float4(pN, tN, eN, 0.f);

        __syncwarp();   // pbuf complete

        // ====== phase 2: lane i sums this half's 32 partials of step t0+i ======
        if (lane < rem) {
            const float4* row = pbuf[lane];
            float x0 = 0.f, x1 = 0.f, x2 = 0.f, x3 = 0.f;
            float y0 = 0.f, y1 = 0.f, y2 = 0.f, y3 = 0.f;
            float z0 = 0.f, z1 = 0.f, z2 = 0.f, z3 = 0.f;
            #pragma unroll
            for (int k = 0; k < 32; k += 4) {
                const float4 v0 = row[k],     v1 = row[k + 1];
                const float4 v2 = row[k + 2], v3 = row[k + 3];
                x0 += v0.x; x1 += v1.x; x2 += v2.x; x3 += v3.x;
                y0 += v0.y; y1 += v1.y; y2 += v2.y; y3 += v3.y;
                z0 += v0.z; z1 += v1.z; z2 += v2.z; z3 += v3.z;
            }
            scr[(size_t)(t0 + lane) * NS] =
                make_float4((x0 + x1) + (x2 + x3),
                            (y0 + y1) + (y2 + y3),
                            (z0 + z1) + (z2 + z3), 0.f);
        }
    }
}

// Combine the two half-partials and emit Q, C, Qs. Fully coalesced.
__global__ void __launch_bounds__(256)
combine_kernel(float* __restrict__ out)
{
    const int idx = blockIdx.x * 256 + threadIdx.x;   // = t*NS + site
    if (idx >= NT * NS) return;

    const float4 va = g_scratch[idx];
    const float4 vb = g_scratch[NT * NS + idx];
    const float Qs1 = va.x + vb.x;
    const float Qs2 = va.y + vb.y;
    const float qc  = va.z + vb.z;
    const float Qk  = Qs1 + Qs2;

    out[idx]         = Qk;
    out[OFF_C + idx] = __fdividef(qc * (1.0f / 64.0f) + 1e-5f, Qk + 1e-5f);
    float* qs = out + OFF_QS + (size_t)idx * 3;
    qs[0] = Qs1;
    qs[1] = Qs2;
    qs[2] = 0.0f;
}

extern "C" void kernel_launch(void* const* d_in, const int* in_sizes, int n_in,
                              void* d_out, int out_size)
{
    (void)in_sizes; (void)n_in; (void)out_size;
    soil_cq_kernel<<<NS * 2, 32>>>(
        (const float*)d_in[0], (const float*)d_in[1], (const float*)d_in[2],
        (const float*)d_in[3], (const float*)d_in[4], (const float*)d_in[5],
        (const float*)d_in[6], (const float*)d_in[7], (const float*)d_in[8],
        (const float*)d_in[9], (const float*)d_in[10],
        (float*)d_out);
    combine_kernel<<<(NT * NS + 255) / 256, 256>>>((float*)d_out);
}

// round 12
// speedup vs baseline: 1.6026x; 1.2253x over previous
#include <cuda_runtime.h>
#include <cuda_bf16.h>

#define NT 2000
#define NS 512
#define NH 64
#define NSNH (NS * NH)

// Output packing (concatenated flattened tuple, float32):
//   Q  : [NT, NS]        at 0
//   C  : [NT, NS]        at 1,024,000
//   S  : [NT, NS, NH]    at 2,048,000
//   H1 : [NT, NS, NH]    at 67,584,000
//   H2 : [NT, NS, NH]    at 133,120,000
//   Qs : [NT, NS, 3]     at 198,656,000
#define OFF_C   1024000
#define OFF_S   2048000
#define OFF_H1  67584000
#define OFF_H2  133120000
#define OFF_QS  198656000

typedef unsigned long long ull;

__device__ __forceinline__ ull PK(float lo, float hi) {
    ull r; asm("mov.b64 %0, {%1,%2};" : "=l"(r) : "f"(lo), "f"(hi)); return r;
}
__device__ __forceinline__ void UPK(float& lo, float& hi, ull v) {
    asm("mov.b64 {%0,%1}, %2;" : "=f"(lo), "=f"(hi) : "l"(v));
}
__device__ __forceinline__ ull ADD2(ull a, ull b) {
    ull r; asm("add.rn.f32x2 %0,%1,%2;" : "=l"(r) : "l"(a), "l"(b)); return r;
}
__device__ __forceinline__ ull MUL2(ull a, ull b) {
    ull r; asm("mul.rn.f32x2 %0,%1,%2;" : "=l"(r) : "l"(a), "l"(b)); return r;
}
__device__ __forceinline__ ull FMA2(ull a, ull b, ull c) {
    ull r; asm("fma.rn.f32x2 %0,%1,%2,%3;" : "=l"(r) : "l"(a), "l"(b), "l"(c)); return r;
}

__device__ __forceinline__ float sigmoidf(float x) {
    return 1.0f / (1.0f + expf(-x));
}

__global__ void __launch_bounds__(32, 8)
soil_cq_kernel(const float* __restrict__ P, const float* __restrict__ T,
               const float* __restrict__ E,
               const float* __restrict__ w,  const float* __restrict__ wk1,
               const float* __restrict__ wk2, const float* __restrict__ we1,
               const float* __restrict__ we2, const float* __restrict__ wl,
               const float* __restrict__ wo,  const float* __restrict__ wc,
               float* __restrict__ out)
{
    const int lane = threadIdx.x;           // 0..31
    const int site = blockIdx.x;            // 0..511
    const int j0 = lane * 2;
    const int j1 = j0 + 1;

    // [step][lane] partials; padded rows for conflict-light transposed reads
    __shared__ float4 pbufA[32][33];        // (qa1.lo, qa1.hi, qa2.lo, qa2.hi)
    __shared__ float2 pbufC[32][33];        // (qc.lo, qc.hi)
    __shared__ float4 fbuf[2][32];          // forcing chunks (p,t,e,_)

    // ---- per-thread parameter precompute (2 hidden units per lane) ----
    const float ew0 = expf(w[j0]) + 1.0f,  ew1 = expf(w[j1]) + 1.0f;
    const float sk10 = sigmoidf(wk1[j0]),  sk11 = sigmoidf(wk1[j1]);
    const float sk20 = sigmoidf(wk2[j0]),  sk21 = sigmoidf(wk2[j1]);
    const float se10 = sigmoidf(we1[j0]),  se11 = sigmoidf(we1[j1]);
    const float se20 = sigmoidf(we2[j0]),  se21 = sigmoidf(we2[j1]);
    const float L0   = expf(wl[j0]),       L1   = expf(wl[j1]);

    // softmax(wo) across the warp's 64 units
    float ex0 = expf(wo[j0]), ex1 = expf(wo[j1]);
    float esum = ex0 + ex1;
    #pragma unroll
    for (int o = 16; o; o >>= 1) esum += __shfl_xor_sync(0xffffffffu, esum, o);
    const float a0 = ex0 / esum, a1 = ex1 / esum;
    const float ar0 = a0 / (sk20 * (1.0f + expf(wc[j0])));
    const float ar1 = a1 / (sk21 * (1.0f + expf(wc[j1])));

    // ---- packed constants ----
    const ull SK1_2  = PK(sk10, sk11);
    const ull SK2_2  = PK(sk20, sk21);
    const ull CSK1_2 = PK(1.0f - sk10, 1.0f - sk11);
    const ull CSK2_2 = PK(1.0f - 2.0f * sk20, 1.0f - 2.0f * sk21);
    const ull NL2    = PK(-L0, -L1);
    const ull A2     = PK(a0, a1);
    const ull AR2    = PK(ar0, ar1);
    const float nse10 = -se10, nse11 = -se11;
    const float nse20 = -se20, nse21 = -se21;

    // ---- state: s scalar pair, h1/h2 packed ----
    float s0 = 0.f, s1 = 0.f;
    ull H1 = PK(0.f, 0.f), H2 = PK(0.f, 0.f);

    // ---- state output pointers (coalesced float2 per warp) ----
    float* Sp  = out + OFF_S  + (size_t)site * NH + j0;
    float* H1p = out + OFF_H1 + (size_t)site * NH + j0;
    float* H2p = out + OFF_H2 + (size_t)site * NH + j0;

    // ---- stage chunk-0 forcings ----
    fbuf[0][lane] = make_float4(P[lane * NS + site],
                                T[lane * NS + site],
                                E[lane * NS + site], 0.f);

// one recurrence step; i is a compile-time-unrolled index -> imm-offset stores
#define STEP(i) do {                                                         \
    const float4 f = fbuf[buf][i];                                           \
    const float p = f.x, t = f.y, e = f.z;                                   \
    const float trel = fmaxf(t, 0.0f);                                       \
    const float ppos = (t > 0.0f) ? p : 0.0f;                                \
    const float pneg = (t < 0.0f) ? p : 0.0f;                                \
    /* s-chain scalar (broadcast-coupled) */                                 \
    const float m0 = fminf(trel * ew0, s0);                                  \
    const float m1 = fminf(trel * ew1, s1);                                  \
    s0 = s0 - m0 + pneg;                                                     \
    s1 = s1 - m1 + pneg;                                                     \
    const float x0 = ppos + m0, x1 = ppos + m1;                              \
    /* packed chain */                                                       \
    const ull X2   = PK(x0, x1);                                             \
    const ull H2X  = ADD2(H2, X2);                                           \
    const ull U2   = ADD2(H1, H2X);                                          \
    const ull UL2  = ADD2(U2, NL2);                                          \
    float ul0, ul1; UPK(ul0, ul1, UL2);                                      \
    const ull H1A  = PK(fmaxf(ul0, 0.f), fmaxf(ul1, 0.f));                   \
    const ull H2Ap = ADD2(H1A, H2X);                                         \
    float ha0, ha1; UPK(ha0, ha1, H2Ap);                                     \
    const ull H2A  = PK(fminf(ha0, L0), fminf(ha1, L1));                     \
    const ull Q1   = MUL2(H1A, SK1_2);                                       \
    const ull Q2   = MUL2(H2A, SK2_2);                                       \
    const float en10 = e * nse10, en11 = e * nse11;                          \
    const float en20 = e * nse20, en21 = e * nse21;                          \
    const ull H1n  = FMA2(H1A, CSK1_2, PK(en10, en11));                      \
    const ull H2n  = FMA2(H2A, CSK2_2, PK(en20, en21));                      \
    float v0, v1, v2, v3;                                                    \
    UPK(v0, v1, H1n); UPK(v2, v3, H2n);                                      \
    const float h10 = fmaxf(v0, 0.f), h11 = fmaxf(v1, 0.f);                  \
    const float h20 = fmaxf(v2, 0.f), h21 = fmaxf(v3, 0.f);                  \
    H1 = PK(h10, h11); H2 = PK(h20, h21);                                    \
    /* streaming state stores, imm offsets */                                \
    __stcs((float2*)(Sp  + (size_t)(i) * NSNH), make_float2(s0,  s1));       \
    __stcs((float2*)(H1p + (size_t)(i) * NSNH), make_float2(h10, h11));      \
    __stcs((float2*)(H2p + (size_t)(i) * NSNH), make_float2(h20, h21));      \
    /* partials */                                                           \
    const ull QA1 = MUL2(Q1, A2);                                            \
    const ull QA2 = MUL2(Q2, A2);                                            \
    const ull QC  = MUL2(Q2, AR2);                                           \
    float w0, w1, w2, w3, c0, c1;                                            \
    UPK(w0, w1, QA1); UPK(w2, w3, QA2); UPK(c0, c1, QC);                     \
    pbufA[i][lane] = make_float4(w0, w1, w2, w3);                            \
    pbufC[i][lane] = make_float2(c0, c1);                                    \
} while (0)

#define PHASE2(REM) do {                                                     \
    if (lane < (REM)) {                                                      \
        const float4* ra = pbufA[lane];                                      \
        const float2* rc = pbufC[lane];                                      \
        float x0 = 0.f, x1 = 0.f, y0 = 0.f, y1 = 0.f, z0 = 0.f, z1 = 0.f;    \
        _Pragma("unroll")                                                    \
        for (int k = 0; k < 32; k += 2) {                                    \
            const float4 va = ra[k],     vb = ra[k + 1];                     \
            const float2 ca = rc[k],     cb = rc[k + 1];                     \
            x0 += va.x + va.y;  x1 += vb.x + vb.y;                           \
            y0 += va.z + va.w;  y1 += vb.z + vb.w;                           \
            z0 += ca.x + ca.y;  z1 += cb.x + cb.y;                           \
        }                                                                    \
        const float Qs1 = x0 + x1;                                           \
        const float Qs2 = y0 + y1;                                           \
        const float qcS = z0 + z1;                                           \
        const float Qk  = Qs1 + Qs2;                                         \
        const float c   = __fdividef(qcS * (1.0f / 64.0f) + 1e-5f,           \
                                     Qk + 1e-5f);                            \
        const int t = t0 + lane;                                             \
        out[t * NS + site]         = Qk;                                     \
        out[OFF_C + t * NS + site] = c;                                      \
        float* qs = out + OFF_QS + ((size_t)t * NS + site) * 3;              \
        qs[0] = Qs1; qs[1] = Qs2; qs[2] = 0.0f;                              \
    }                                                                        \
} while (0)

    #pragma unroll 1
    for (int c62 = 0; c62 < 62; ++c62) {
        const int t0  = c62 * 32;
        const int buf = c62 & 1;

        // prefetch next chunk's forcings into registers
        float pN = 0.f, tN = 0.f, eN = 0.f;
        {
            const int tn = t0 + 32 + lane;
            if (tn < NT) {
                pN = P[tn * NS + site];
                tN = T[tn * NS + site];
                eN = E[tn * NS + site];
            }
        }

        __syncwarp();   // fbuf[buf] staged; prev phase-2 done with pbuf

        #pragma unroll
        for (int i = 0; i < 32; ++i) STEP(i);

        Sp  += 32 * NSNH;
        H1p += 32 * NSNH;
        H2p += 32 * NSNH;

        fbuf[buf ^ 1][lane] = make_float4(pN, tN, eN, 0.f);

        __syncwarp();   // pbuf complete

        PHASE2(32);
    }

    // ---- tail chunk: t0 = 1984, 16 steps, buf = 0 (62 & 1) ----
    {
        const int t0  = 1984;
        const int buf = 0;
        __syncwarp();
        #pragma unroll
        for (int i = 0; i < 16; ++i) STEP(i);
        __syncwarp();
        PHASE2(16);
    }

#undef STEP
#undef PHASE2
}

extern "C" void kernel_launch(void* const* d_in, const int* in_sizes, int n_in,
                              void* d_out, int out_size)
{
    (void)in_sizes; (void)n_in; (void)out_size;
    soil_cq_kernel<<<NS, 32>>>(
        (const float*)d_in[0], (const float*)d_in[1], (const float*)d_in[2],
        (const float*)d_in[3], (const float*)d_in[4], (const float*)d_in[5],
        (const float*)d_in[6], (const float*)d_in[7], (const float*)d_in[8],
        (const float*)d_in[9], (const float*)d_in[10],
        (float*)d_out);
}